// round 15
// baseline (speedup 1.0000x reference)
#include <cuda_runtime.h>
#include <math.h>

#define BATCH 32
#define SEQT  512
#define HID   512
#define G4    2048   // 4*HID

// out layout (fp32): out[B][T][2H] @0, h_n[2][B][H] @16777216, c_n @16809984
#define OUT_HN 16777216
#define OUT_CN 16809984

// ---------------------------------------------------------------------------
// Device globals (allocation-free scratch), 256B-aligned for vector access.
// ---------------------------------------------------------------------------
// gx permuted per consumer block: [dir][bh][blk(32)][t][cl(64)][bl(16)]
__device__ __align__(256) float g_gx[2][2][32][SEQT][64][16];
// h ping-pong: [parity][dir][bh][bl(16)][unit(512)] (linear == h0 layout)
__device__ __align__(256) float g_hB[2][2][2][16][HID];
// grouped step counters: stream=(dir,bh): 4 groups x 8 blocks, 128B line each
// group g covers unit range [128g, 128g+128) of the stream
__device__ __align__(256) int   g_cnt[2][2][4][32];

// ---------------------------------------------------------------------------
// Packed fp32x2 FMA (Blackwell FFMA2; only reachable via PTX)
// ---------------------------------------------------------------------------
__device__ __forceinline__ float2 f2fma(float2 a, float2 b, float2 c) {
    unsigned long long ra = *reinterpret_cast<unsigned long long*>(&a);
    unsigned long long rb = *reinterpret_cast<unsigned long long*>(&b);
    unsigned long long rc = *reinterpret_cast<unsigned long long*>(&c);
    unsigned long long rd;
    asm("fma.rn.f32x2 %0, %1, %2, %3;" : "=l"(rd) : "l"(ra), "l"(rb), "l"(rc));
    return *reinterpret_cast<float2*>(&rd);
}
__device__ __forceinline__ float2 f2(float x, float y) { return make_float2(x, y); }

__device__ __forceinline__ float sigf(float x) { return 1.0f / (1.0f + __expf(-x)); }
__device__ __forceinline__ float tanhx(float x) { return 2.0f / (1.0f + __expf(-2.0f * x)) - 1.0f; }

// ---------------------------------------------------------------------------
// Phase 1: gx = x @ W_ih^T + biases (written permuted). Init embedded.
// BM=BN=64, BK=16, 256 thr, 4x4 microtile, dup'd-A f32x2 (unchanged).
// ---------------------------------------------------------------------------
#define BM 64
#define BN 64
#define BK 16

__global__ __launch_bounds__(256) void gemm_ih_kernel(
        const float* __restrict__ x,
        const float* __restrict__ h0,
        const float* __restrict__ w_f, const float* __restrict__ w_r,
        const float* __restrict__ bi_f, const float* __restrict__ bh_f,
        const float* __restrict__ bi_r, const float* __restrict__ bh_r) {
    const int tid = threadIdx.x;

    // ---- embedded init (h0 -> g_hB[0] (identical linear layout), counters) ----
    {
        const int gid = (blockIdx.z * gridDim.y + blockIdx.y) * gridDim.x + blockIdx.x;
        if (gid < 128) {
            const int idx = gid * 256 + tid;     // 0..32767
            (&g_hB[0][0][0][0][0])[idx] = h0[idx];
        }
        if (gid == 0 && tid < 16)
            g_cnt[tid >> 3][(tid >> 2) & 1][tid & 3][0] = 0;
    }

    const int dir = blockIdx.z;
    const float* __restrict__ w  = dir ? w_r  : w_f;
    const float* __restrict__ bi = dir ? bi_r : bi_f;
    const float* __restrict__ bh = dir ? bh_r : bh_f;

    const int rm0 = blockIdx.y * BM;   // rows over T*B (row = t*32+b)
    const int cn0 = blockIdx.x * BN;   // cols over 4H

    __shared__ __align__(16) float2 Asd[BK][BM + 2];   // A rows, duplicated lanes
    __shared__ __align__(16) float  Ws[BK][BN + 4];

    const int tr = tid / 16;           // 0..15 row group
    const int tc = tid % 16;           // 0..15 col group

    const int l_row = tid >> 2;        // 0..63
    const int l_k4  = (tid & 3) << 2;  // 0,4,8,12

    const int r  = rm0 + l_row;
    int       tt = r >> 5;
    const int bb = r & 31;
    if (dir) tt = (SEQT - 1) - tt;
    const float* a_ptr = x + ((size_t)bb * SEQT + tt) * HID;
    const float* w_ptr = w + (size_t)(cn0 + l_row) * HID;

    float2 acc[4][2];
#pragma unroll
    for (int i = 0; i < 4; i++) { acc[i][0] = f2(0.f, 0.f); acc[i][1] = f2(0.f, 0.f); }

    for (int k0 = 0; k0 < HID; k0 += BK) {
        float4 av = *(const float4*)(a_ptr + k0 + l_k4);
        float4 wv = *(const float4*)(w_ptr + k0 + l_k4);
        __syncthreads();
        Asd[l_k4 + 0][l_row] = f2(av.x, av.x);
        Asd[l_k4 + 1][l_row] = f2(av.y, av.y);
        Asd[l_k4 + 2][l_row] = f2(av.z, av.z);
        Asd[l_k4 + 3][l_row] = f2(av.w, av.w);
        Ws[l_k4 + 0][l_row] = wv.x;
        Ws[l_k4 + 1][l_row] = wv.y;
        Ws[l_k4 + 2][l_row] = wv.z;
        Ws[l_k4 + 3][l_row] = wv.w;
        __syncthreads();
#pragma unroll
        for (int kk = 0; kk < BK; kk++) {
            float4 ad0 = *(const float4*)&Asd[kk][tr * 4];
            float4 ad1 = *(const float4*)&Asd[kk][tr * 4 + 2];
            float4 w4  = *(const float4*)&Ws[kk][tc * 4];
            float2 w01 = f2(w4.x, w4.y);
            float2 w23 = f2(w4.z, w4.w);
            float2 a0 = f2(ad0.x, ad0.y);
            float2 a1 = f2(ad0.z, ad0.w);
            float2 a2 = f2(ad1.x, ad1.y);
            float2 a3 = f2(ad1.z, ad1.w);
            acc[0][0] = f2fma(a0, w01, acc[0][0]); acc[0][1] = f2fma(a0, w23, acc[0][1]);
            acc[1][0] = f2fma(a1, w01, acc[1][0]); acc[1][1] = f2fma(a1, w23, acc[1][1]);
            acc[2][0] = f2fma(a2, w01, acc[2][0]); acc[2][1] = f2fma(a2, w23, acc[2][1]);
            acc[3][0] = f2fma(a3, w01, acc[3][0]); acc[3][1] = f2fma(a3, w23, acc[3][1]);
        }
    }

    // epilogue: permuted gx. col c: unit=c&511, gate=c>>9;
    //   blk = unit>>4, cl = gate*16 + (unit&15); bh=b>>4, bl=b&15
    const int cc = cn0 + tc * 4;
    float bsum[4], res[4];
#pragma unroll
    for (int j = 0; j < 4; j++) bsum[j] = bi[cc + j] + bh[cc + j];
#pragma unroll
    for (int i = 0; i < 4; i++) {
        const int rr = rm0 + tr * 4 + i;
        const int t = rr >> 5;
        const int b = rr & 31;
        const int bhh = b >> 4;
        const int bl = b & 15;
        res[0] = acc[i][0].x + bsum[0];
        res[1] = acc[i][0].y + bsum[1];
        res[2] = acc[i][1].x + bsum[2];
        res[3] = acc[i][1].y + bsum[3];
#pragma unroll
        for (int j = 0; j < 4; j++) {
            const int c = cc + j;
            const int unit = c & 511;
            const int gate = c >> 9;
            const int blk = unit >> 4;
            const int cl = gate * 16 + (unit & 15);
            g_gx[dir][bhh][blk][t][cl][bl] = res[j];
        }
    }
}

// ---------------------------------------------------------------------------
// Phase 2: persistent recurrence. 4 streams (dir x batch-half) x 32 blocks;
// block owns 16 units x 16 batches. W-in-registers GEMM.
// NEW: 2-chunk pipelined wait — chunk ck waits only counter groups {2ck,2ck+1}
// (units [256ck, 256ck+256)), stages 16KB, computes jp [4ck,4ck+4), so the
// second chunk's skew/detect hides behind the first chunk's compute.
// ---------------------------------------------------------------------------
#define NBLK 128
#define PST 17                     // P row stride (floats); scalar access only
#define PHALF (64 * PST)           // chunk-1 partial offset

#define SM_HS 0                    // float Hs[16][512]    = 32768 B
#define SM_P  32768                // float P[2][64][17]   =  8704 B
#define SM_HO 41472                // float HO[16][16]     =  1024 B
#define SMEM_TOTAL (41472 + 1024)

__global__ __launch_bounds__(256, 1)
void lstm_persistent_kernel(const float* __restrict__ w_hh_f,
                            const float* __restrict__ w_hh_r,
                            const float* __restrict__ c0,
                            float* __restrict__ out) {
    extern __shared__ __align__(16) char smem_raw[];
    float* Hs = (float*)(smem_raw + SM_HS);    // [bl][k], stride 512
    float* P  = (float*)(smem_raw + SM_P);     // [ck][cl][bl], stride PST
    float* HO = (float*)(smem_raw + SM_HO);    // [bl][16]

    const int tid = threadIdx.x;
    const int b128 = blockIdx.x;               // 0..127
    const int dir = b128 >> 6;
    const int bh  = (b128 >> 5) & 1;
    const int blk = b128 & 31;
    const int j0  = blk * 16;
    const float* __restrict__ w = dir ? w_hh_r : w_hh_f;

    const int wid  = tid >> 5;                 // 0..7
    const int lane = tid & 31;
    const int uh   = wid >> 2;                 // unit half (8 units)
    const int gate = wid & 3;

    // ---- W registers: warp covers cols gate*512 + [j0+uh*8, +8), lane=k%32 ----
    float2 wreg[8][8];
#pragma unroll
    for (int c8 = 0; c8 < 8; c8++) {
        const float* wr = w + (size_t)(gate * HID + j0 + uh * 8 + c8) * HID;
#pragma unroll
        for (int jp = 0; jp < 8; jp++)
            wreg[c8][jp] = f2(wr[jp * 64 + lane], wr[jp * 64 + 32 + lane]);
    }

    // butterfly constants: cmap from lane bits {4,3,2}; owner lane&3==0
    const bool hi16 = (lane & 16) != 0;
    const bool hi8  = (lane & 8)  != 0;
    const bool hi4  = (lane & 4)  != 0;
    const int  cmap = ((lane >> 4) & 1) * 4 + ((lane >> 3) & 1) * 2 + ((lane >> 2) & 1);
    float* pdst = &P[(gate * 16 + uh * 8 + cmap) * PST];

    // ---- pointwise: 256 threads = 16 units x 16 batches ----
    const int pu = tid >> 4;                   // 0..15 local unit
    const int pb = tid & 15;                   // 0..15 local batch
    float creg = c0[((size_t)dir * BATCH + bh * 16 + pb) * HID + j0 + pu];

    const float* gxbase = &g_gx[dir][bh][blk][0][0][0];
    int* mycnt = &g_cnt[dir][bh][blk >> 3][0];

    __syncthreads();

    for (int t = 0; t < SEQT; t++) {
        // prefetch gx (coalesced per half-warp; in flight during the wait)
        const float* gxp = gxbase + (size_t)t * 1024;
        float gxr0 = gxp[(pu)      * 16 + pb];
        float gxr1 = gxp[(16 + pu) * 16 + pb];
        float gxr2 = gxp[(32 + pu) * 16 + pb];
        float gxr3 = gxp[(48 + pu) * 16 + pb];

        const float* srcb = &g_hB[t & 1][dir][bh][0][0];

        // -------- two pipelined chunks over k --------
#pragma unroll
        for (int ck = 0; ck < 2; ck++) {
            // wait: 2 lanes poll this chunk's 2 producer-group counters
            if (t > 0 && tid < 2) {
                int* pc = &g_cnt[dir][bh][ck * 2 + tid][0];
                const int target = 8 * t;
                int v;
                do {
                    asm volatile("ld.acquire.gpu.s32 %0, [%1];" : "=r"(v) : "l"(pc));
                } while (v < target);
            }
            __syncthreads();

            // stage chunk: 16KB = 16 rows x 256 floats (k range [256ck, +256))
            // 1024 float4, 256 threads -> 4 each, coalesced (64 f4 per row)
#pragma unroll
            for (int it = 0; it < 4; it++) {
                const int idx = it * 256 + tid;      // 0..1023
                const int bl = idx >> 6;
                const int kq = idx & 63;
                *(float4*)&Hs[bl * 512 + ck * 256 + kq * 4] =
                    *(const float4*)&srcb[bl * 512 + ck * 256 + kq * 4];
            }
            __syncthreads();

            // GEMM chunk: 16 batches x 8 cols x 256 k (jp in [4ck, 4ck+4))
            const float* hbase = Hs + ck * 256 + lane;
            float* pck = pdst + ck * PHALF;
#pragma unroll 4
            for (int bi = 0; bi < 16; bi++) {
                const float* hp = hbase + bi * 512;
                float2 a0 = f2(0.f, 0.f), a1 = f2(0.f, 0.f), a2 = f2(0.f, 0.f), a3 = f2(0.f, 0.f);
                float2 a4 = f2(0.f, 0.f), a5 = f2(0.f, 0.f), a6 = f2(0.f, 0.f), a7 = f2(0.f, 0.f);
#pragma unroll
                for (int jq = 0; jq < 4; jq++) {
                    const int jp = ck * 4 + jq;
                    float2 hv = f2(hp[jq * 64], hp[jq * 64 + 32]);
                    a0 = f2fma(hv, wreg[0][jp], a0);
                    a1 = f2fma(hv, wreg[1][jp], a1);
                    a2 = f2fma(hv, wreg[2][jp], a2);
                    a3 = f2fma(hv, wreg[3][jp], a3);
                    a4 = f2fma(hv, wreg[4][jp], a4);
                    a5 = f2fma(hv, wreg[5][jp], a5);
                    a6 = f2fma(hv, wreg[6][jp], a6);
                    a7 = f2fma(hv, wreg[7][jp], a7);
                }
                float v0 = a0.x + a0.y, v1 = a1.x + a1.y, v2 = a2.x + a2.y, v3 = a3.x + a3.y;
                float v4 = a4.x + a4.y, v5 = a5.x + a5.y, v6 = a6.x + a6.y, v7 = a7.x + a7.y;

                // value-halving butterfly over lanes (k-residues)
                float k0 = hi16 ? v4 : v0,  s0 = hi16 ? v0 : v4;
                float k1 = hi16 ? v5 : v1,  s1 = hi16 ? v1 : v5;
                float k2 = hi16 ? v6 : v2,  s2 = hi16 ? v2 : v6;
                float k3 = hi16 ? v7 : v3,  s3 = hi16 ? v3 : v7;
                k0 += __shfl_xor_sync(0xffffffffu, s0, 16);
                k1 += __shfl_xor_sync(0xffffffffu, s1, 16);
                k2 += __shfl_xor_sync(0xffffffffu, s2, 16);
                k3 += __shfl_xor_sync(0xffffffffu, s3, 16);
                float m0 = hi8 ? k2 : k0,  t0 = hi8 ? k0 : k2;
                float m1 = hi8 ? k3 : k1,  t1 = hi8 ? k1 : k3;
                m0 += __shfl_xor_sync(0xffffffffu, t0, 8);
                m1 += __shfl_xor_sync(0xffffffffu, t1, 8);
                float m = hi4 ? m1 : m0,  u = hi4 ? m0 : m1;
                m += __shfl_xor_sync(0xffffffffu, u, 4);
                m += __shfl_xor_sync(0xffffffffu, m, 2);
                m += __shfl_xor_sync(0xffffffffu, m, 1);
                if ((lane & 3) == 0) pck[bi] = m;
            }
        }
        __syncthreads();

        // pointwise: 1 (unit,batch) per thread; sum the two chunk partials
        {
            const float pi = P[(pu)      * PST + pb] + P[PHALF + (pu)      * PST + pb] + gxr0;
            const float pf = P[(16 + pu) * PST + pb] + P[PHALF + (16 + pu) * PST + pb] + gxr1;
            const float pg = P[(32 + pu) * PST + pb] + P[PHALF + (32 + pu) * PST + pb] + gxr2;
            const float po = P[(48 + pu) * PST + pb] + P[PHALF + (48 + pu) * PST + pb] + gxr3;
            const float iv = sigf(pi);
            const float fv = sigf(pf);
            const float gv = tanhx(pg);
            const float ov = sigf(po);
            creg = fv * creg + iv * gv;
            const float hnew = ov * tanhx(creg);
            HO[pb * 16 + pu] = hnew;
            if (t == SEQT - 1) {
                out[OUT_HN + ((size_t)dir * BATCH + bh * 16 + pb) * HID + j0 + pu] = hnew;
                out[OUT_CN + ((size_t)dir * BATCH + bh * 16 + pb) * HID + j0 + pu] = creg;
            }
        }
        __syncthreads();   // HO visible

        // h write (64 threads x float4), then signal, then out (off crit path)
        if (tid < 64) {
            const int b  = tid >> 2;
            const int sg = (tid & 3) * 4;
            float4 v = *(const float4*)&HO[b * 16 + sg];
            float* hdst = &g_hB[(t & 1) ^ 1][dir][bh][b][0];
            *(float4*)&hdst[j0 + sg] = v;
        }
        __syncthreads();   // h stores block-wide before release

        if (tid == 0) {
            asm volatile("red.release.gpu.add.s32 [%0], %1;"
                         :: "l"(mycnt), "r"(1));
        }

        if (tid < 64) {
            const int b  = tid >> 2;
            const int sg = (tid & 3) * 4;
            float4 v = *(const float4*)&HO[b * 16 + sg];
            const int tout = dir ? (SEQT - 1 - t) : t;
            *(float4*)&out[((size_t)(bh * 16 + b) * SEQT + tout) * (2 * HID)
                           + dir * HID + j0 + sg] = v;
        }
    }
}

// ---------------------------------------------------------------------------
// Launch
// ---------------------------------------------------------------------------
extern "C" void kernel_launch(void* const* d_in, const int* in_sizes, int n_in,
                              void* d_out, int out_size) {
    const float* x      = (const float*)d_in[0];
    const float* h0     = (const float*)d_in[1];
    const float* c0     = (const float*)d_in[2];
    const float* w_ih_f = (const float*)d_in[3];
    const float* w_hh_f = (const float*)d_in[4];
    const float* b_ih_f = (const float*)d_in[5];
    const float* b_hh_f = (const float*)d_in[6];
    const float* w_ih_r = (const float*)d_in[7];
    const float* w_hh_r = (const float*)d_in[8];
    const float* b_ih_r = (const float*)d_in[9];
    const float* b_hh_r = (const float*)d_in[10];
    float* out = (float*)d_out;

    cudaFuncSetAttribute(lstm_persistent_kernel,
                         cudaFuncAttributeMaxDynamicSharedMemorySize, SMEM_TOTAL);

    dim3 ggrid(G4 / BN, (SEQT * BATCH) / BM, 2);   // (32, 256, 2)
    gemm_ih_kernel<<<ggrid, 256>>>(x, h0, w_ih_f, w_ih_r,
                                   b_ih_f, b_hh_f, b_ih_r, b_hh_r);

    lstm_persistent_kernel<<<NBLK, 256, SMEM_TOTAL>>>(
        w_hh_f, w_hh_r, c0, out);
}

// round 16
// speedup vs baseline: 1.1845x; 1.1845x over previous
#include <cuda_runtime.h>
#include <math.h>

#define BATCH 32
#define SEQT  512
#define HID   512
#define G4    2048   // 4*HID

// out layout (fp32): out[B][T][2H] @0, h_n[2][B][H] @16777216, c_n @16809984
#define OUT_HN 16777216
#define OUT_CN 16809984

// ---------------------------------------------------------------------------
// Device globals (allocation-free scratch), 256B-aligned for vector access.
// ---------------------------------------------------------------------------
// gx permuted per consumer half-block: [dir][bh][ublk(64)][t][cl(32)][bl(16)]
__device__ __align__(256) float g_gx[2][2][64][SEQT][32][16];
// h ping-pong: [parity][dir][bh][bl(16)][unit(512)] (linear == h0 layout)
__device__ __align__(256) float g_hB[2][2][2][16][HID];
// grouped step counters: stream=(dir,bh): 8 groups x 8 half-blocks, 128B lines
__device__ __align__(256) int   g_cnt[2][2][8][32];

// ---------------------------------------------------------------------------
// Packed fp32x2 FMA (Blackwell FFMA2; only reachable via PTX)
// ---------------------------------------------------------------------------
__device__ __forceinline__ float2 f2fma(float2 a, float2 b, float2 c) {
    unsigned long long ra = *reinterpret_cast<unsigned long long*>(&a);
    unsigned long long rb = *reinterpret_cast<unsigned long long*>(&b);
    unsigned long long rc = *reinterpret_cast<unsigned long long*>(&c);
    unsigned long long rd;
    asm("fma.rn.f32x2 %0, %1, %2, %3;" : "=l"(rd) : "l"(ra), "l"(rb), "l"(rc));
    return *reinterpret_cast<float2*>(&rd);
}
__device__ __forceinline__ float2 f2(float x, float y) { return make_float2(x, y); }

__device__ __forceinline__ float sigf(float x) { return 1.0f / (1.0f + __expf(-x)); }
__device__ __forceinline__ float tanhx(float x) { return 2.0f / (1.0f + __expf(-2.0f * x)) - 1.0f; }

// named barrier for one 128-thread half (id 1 or 2)
__device__ __forceinline__ void barh(int id) {
    asm volatile("bar.sync %0, 128;" :: "r"(id) : "memory");
}

// ---------------------------------------------------------------------------
// Phase 1: gx = x @ W_ih^T + biases (written permuted). Init embedded.
// BM=BN=64, BK=16, 256 thr, 4x4 microtile, dup'd-A f32x2 (unchanged).
// ---------------------------------------------------------------------------
#define BM 64
#define BN 64
#define BK 16

__global__ __launch_bounds__(256) void gemm_ih_kernel(
        const float* __restrict__ x,
        const float* __restrict__ h0,
        const float* __restrict__ w_f, const float* __restrict__ w_r,
        const float* __restrict__ bi_f, const float* __restrict__ bh_f,
        const float* __restrict__ bi_r, const float* __restrict__ bh_r) {
    const int tid = threadIdx.x;

    // ---- embedded init (h0 -> g_hB[0] (identical linear layout), counters) ----
    {
        const int gid = (blockIdx.z * gridDim.y + blockIdx.y) * gridDim.x + blockIdx.x;
        if (gid < 128) {
            const int idx = gid * 256 + tid;     // 0..32767
            (&g_hB[0][0][0][0][0])[idx] = h0[idx];
        }
        if (gid == 0 && tid < 32)
            g_cnt[tid >> 4][(tid >> 3) & 1][tid & 7][0] = 0;
    }

    const int dir = blockIdx.z;
    const float* __restrict__ w  = dir ? w_r  : w_f;
    const float* __restrict__ bi = dir ? bi_r : bi_f;
    const float* __restrict__ bh = dir ? bh_r : bh_f;

    const int rm0 = blockIdx.y * BM;   // rows over T*B (row = t*32+b)
    const int cn0 = blockIdx.x * BN;   // cols over 4H

    __shared__ __align__(16) float2 Asd[BK][BM + 2];   // A rows, duplicated lanes
    __shared__ __align__(16) float  Ws[BK][BN + 4];

    const int tr = tid / 16;           // 0..15 row group
    const int tc = tid % 16;           // 0..15 col group

    const int l_row = tid >> 2;        // 0..63
    const int l_k4  = (tid & 3) << 2;  // 0,4,8,12

    const int r  = rm0 + l_row;
    int       tt = r >> 5;
    const int bb = r & 31;
    if (dir) tt = (SEQT - 1) - tt;
    const float* a_ptr = x + ((size_t)bb * SEQT + tt) * HID;
    const float* w_ptr = w + (size_t)(cn0 + l_row) * HID;

    float2 acc[4][2];
#pragma unroll
    for (int i = 0; i < 4; i++) { acc[i][0] = f2(0.f, 0.f); acc[i][1] = f2(0.f, 0.f); }

    for (int k0 = 0; k0 < HID; k0 += BK) {
        float4 av = *(const float4*)(a_ptr + k0 + l_k4);
        float4 wv = *(const float4*)(w_ptr + k0 + l_k4);
        __syncthreads();
        Asd[l_k4 + 0][l_row] = f2(av.x, av.x);
        Asd[l_k4 + 1][l_row] = f2(av.y, av.y);
        Asd[l_k4 + 2][l_row] = f2(av.z, av.z);
        Asd[l_k4 + 3][l_row] = f2(av.w, av.w);
        Ws[l_k4 + 0][l_row] = wv.x;
        Ws[l_k4 + 1][l_row] = wv.y;
        Ws[l_k4 + 2][l_row] = wv.z;
        Ws[l_k4 + 3][l_row] = wv.w;
        __syncthreads();
#pragma unroll
        for (int kk = 0; kk < BK; kk++) {
            float4 ad0 = *(const float4*)&Asd[kk][tr * 4];
            float4 ad1 = *(const float4*)&Asd[kk][tr * 4 + 2];
            float4 w4  = *(const float4*)&Ws[kk][tc * 4];
            float2 w01 = f2(w4.x, w4.y);
            float2 w23 = f2(w4.z, w4.w);
            float2 a0 = f2(ad0.x, ad0.y);
            float2 a1 = f2(ad0.z, ad0.w);
            float2 a2 = f2(ad1.x, ad1.y);
            float2 a3 = f2(ad1.z, ad1.w);
            acc[0][0] = f2fma(a0, w01, acc[0][0]); acc[0][1] = f2fma(a0, w23, acc[0][1]);
            acc[1][0] = f2fma(a1, w01, acc[1][0]); acc[1][1] = f2fma(a1, w23, acc[1][1]);
            acc[2][0] = f2fma(a2, w01, acc[2][0]); acc[2][1] = f2fma(a2, w23, acc[2][1]);
            acc[3][0] = f2fma(a3, w01, acc[3][0]); acc[3][1] = f2fma(a3, w23, acc[3][1]);
        }
    }

    // epilogue: permuted gx. col c: unit=c&511, gate=c>>9;
    //   ublk = unit>>3, cl = gate*8 + (unit&7); bh=b>>4, bl=b&15
    const int cc = cn0 + tc * 4;
    float bsum[4], res[4];
#pragma unroll
    for (int j = 0; j < 4; j++) bsum[j] = bi[cc + j] + bh[cc + j];
#pragma unroll
    for (int i = 0; i < 4; i++) {
        const int rr = rm0 + tr * 4 + i;
        const int t = rr >> 5;
        const int b = rr & 31;
        const int bhh = b >> 4;
        const int bl = b & 15;
        res[0] = acc[i][0].x + bsum[0];
        res[1] = acc[i][0].y + bsum[1];
        res[2] = acc[i][1].x + bsum[2];
        res[3] = acc[i][1].y + bsum[3];
#pragma unroll
        for (int j = 0; j < 4; j++) {
            const int c = cc + j;
            const int unit = c & 511;
            const int gate = c >> 9;
            const int ublk = unit >> 3;
            const int cl = gate * 8 + (unit & 7);
            g_gx[dir][bhh][ublk][t][cl][bl] = res[j];
        }
    }
}

// ---------------------------------------------------------------------------
// Phase 2: persistent recurrence. 128 blocks x 256 threads; each block = TWO
// independent 128-thread halves: half h runs dir h's stream (same bh, same
// 8-unit slice). Each half: own wait/stage/GEMM/pointwise/signal with a named
// barrier — while one half spins on its producers, the other half's warps
// keep the SMSPs busy (1 warp of each half per SMSP).
// ---------------------------------------------------------------------------
#define NBLK 128
#define PST 17                     // P row stride (floats); scalar access only

#define SM_HS 0                    // float Hs[2][16][512] = 65536 B
#define SM_P  65536                // float P[2][32][17]   =  4352 B
#define SM_HO 69888                // float HO[2][16][8]   =  1024 B
#define SMEM_TOTAL (69888 + 1024)

__global__ __launch_bounds__(256, 1)
void lstm_persistent_kernel(const float* __restrict__ w_hh_f,
                            const float* __restrict__ w_hh_r,
                            const float* __restrict__ c0,
                            float* __restrict__ out) {
    extern __shared__ __align__(16) char smem_raw[];

    const int tid  = threadIdx.x;
    const int half = tid >> 7;                 // 0/1 = dir
    const int tid7 = tid & 127;
    const int dir  = half;
    const int bh   = blockIdx.x >> 6;          // batch half
    const int ublk = blockIdx.x & 63;          // unit block (8 units)
    const int j0   = ublk * 8;
    const int barid = 1 + half;
    const float* __restrict__ w = dir ? w_hh_r : w_hh_f;

    float* Hs = (float*)(smem_raw + SM_HS) + half * (16 * 512);  // [bl][k]
    float* P  = (float*)(smem_raw + SM_P)  + half * (32 * PST);  // [cl][bl]
    float* HO = (float*)(smem_raw + SM_HO) + half * 128;         // [bl][8]

    const int wih  = (tid7 >> 5);              // warp-in-half = gate 0..3
    const int lane = tid & 31;

    // ---- W registers: warp = gate; 8 cols = units [j0, j0+8); lane = k%32 ----
    float2 wreg[8][8];
#pragma unroll
    for (int c8 = 0; c8 < 8; c8++) {
        const float* wr = w + (size_t)(wih * HID + j0 + c8) * HID;
#pragma unroll
        for (int jp = 0; jp < 8; jp++)
            wreg[c8][jp] = f2(wr[jp * 64 + lane], wr[jp * 64 + 32 + lane]);
    }

    // butterfly constants: cmap from lane bits {4,3,2}; owner lane&3==0
    const bool hi16 = (lane & 16) != 0;
    const bool hi8  = (lane & 8)  != 0;
    const bool hi4  = (lane & 4)  != 0;
    const int  cmap = ((lane >> 4) & 1) * 4 + ((lane >> 3) & 1) * 2 + ((lane >> 2) & 1);
    float* pdst = &P[(wih * 8 + cmap) * PST];

    // ---- pointwise: 128 threads of the half = 8 units x 16 batches ----
    const int pu = tid7 >> 4;                  // 0..7 local unit
    const int pb = tid7 & 15;                  // 0..15 local batch
    float creg = c0[((size_t)dir * BATCH + bh * 16 + pb) * HID + j0 + pu];

    const float* gxbase = &g_gx[dir][bh][ublk][0][0][0];
    int* mycnt = &g_cnt[dir][bh][ublk >> 3][0];

    __syncthreads();   // W/creg loads done in both halves before the loop

    for (int t = 0; t < SEQT; t++) {
        // prefetch gx (coalesced; in flight during the wait)
        const float* gxp = gxbase + (size_t)t * 512;
        float gxr0 = gxp[(pu)      * 16 + pb];
        float gxr1 = gxp[(8 + pu)  * 16 + pb];
        float gxr2 = gxp[(16 + pu) * 16 + pb];
        float gxr3 = gxp[(24 + pu) * 16 + pb];

        // wait: 8 lanes poll this stream's 8 grouped counters (8 halves each)
        if (t > 0 && tid7 < 8) {
            int* pc = &g_cnt[dir][bh][tid7][0];
            const int target = 8 * t;
            int v;
            do {
                asm volatile("ld.acquire.gpu.s32 %0, [%1];" : "=r"(v) : "l"(pc));
            } while (v < target);
        }
        barh(barid);

        // stage h (32KB) into Hs[bl][k] — linear coalesced copy, 128 threads
        {
            const float4* src = (const float4*)&g_hB[t & 1][dir][bh][0][0];
            float4* dst4 = (float4*)Hs;
#pragma unroll
            for (int it = 0; it < 16; it++) dst4[it * 128 + tid7] = src[it * 128 + tid7];
        }
        barh(barid);

        // GEMM: 16 batches x 8 cols x 512 k per warp (R14-proven shape)
        const float* hbase = Hs + lane;
#pragma unroll 4
        for (int bi = 0; bi < 16; bi++) {
            const float* hp = hbase + bi * 512;
            float2 a0 = f2(0.f, 0.f), a1 = f2(0.f, 0.f), a2 = f2(0.f, 0.f), a3 = f2(0.f, 0.f);
            float2 a4 = f2(0.f, 0.f), a5 = f2(0.f, 0.f), a6 = f2(0.f, 0.f), a7 = f2(0.f, 0.f);
#pragma unroll
            for (int jp = 0; jp < 8; jp++) {
                float2 hv = f2(hp[jp * 64], hp[jp * 64 + 32]);
                a0 = f2fma(hv, wreg[0][jp], a0);
                a1 = f2fma(hv, wreg[1][jp], a1);
                a2 = f2fma(hv, wreg[2][jp], a2);
                a3 = f2fma(hv, wreg[3][jp], a3);
                a4 = f2fma(hv, wreg[4][jp], a4);
                a5 = f2fma(hv, wreg[5][jp], a5);
                a6 = f2fma(hv, wreg[6][jp], a6);
                a7 = f2fma(hv, wreg[7][jp], a7);
            }
            float v0 = a0.x + a0.y, v1 = a1.x + a1.y, v2 = a2.x + a2.y, v3 = a3.x + a3.y;
            float v4 = a4.x + a4.y, v5 = a5.x + a5.y, v6 = a6.x + a6.y, v7 = a7.x + a7.y;

            // value-halving butterfly over lanes (k-residues)
            float k0 = hi16 ? v4 : v0,  s0 = hi16 ? v0 : v4;
            float k1 = hi16 ? v5 : v1,  s1 = hi16 ? v1 : v5;
            float k2 = hi16 ? v6 : v2,  s2 = hi16 ? v2 : v6;
            float k3 = hi16 ? v7 : v3,  s3 = hi16 ? v3 : v7;
            k0 += __shfl_xor_sync(0xffffffffu, s0, 16);
            k1 += __shfl_xor_sync(0xffffffffu, s1, 16);
            k2 += __shfl_xor_sync(0xffffffffu, s2, 16);
            k3 += __shfl_xor_sync(0xffffffffu, s3, 16);
            float m0 = hi8 ? k2 : k0,  t0 = hi8 ? k0 : k2;
            float m1 = hi8 ? k3 : k1,  t1 = hi8 ? k1 : k3;
            m0 += __shfl_xor_sync(0xffffffffu, t0, 8);
            m1 += __shfl_xor_sync(0xffffffffu, t1, 8);
            float m = hi4 ? m1 : m0,  u = hi4 ? m0 : m1;
            m += __shfl_xor_sync(0xffffffffu, u, 4);
            m += __shfl_xor_sync(0xffffffffu, m, 2);
            m += __shfl_xor_sync(0xffffffffu, m, 1);
            if ((lane & 3) == 0) pdst[bi] = m;
        }
        barh(barid);

        // pointwise: 1 (unit,batch) per thread of the half
        {
            const float pi = P[(pu)      * PST + pb] + gxr0;
            const float pf = P[(8 + pu)  * PST + pb] + gxr1;
            const float pg = P[(16 + pu) * PST + pb] + gxr2;
            const float po = P[(24 + pu) * PST + pb] + gxr3;
            const float iv = sigf(pi);
            const float fv = sigf(pf);
            const float gv = tanhx(pg);
            const float ov = sigf(po);
            creg = fv * creg + iv * gv;
            const float hnew = ov * tanhx(creg);
            HO[pb * 8 + pu] = hnew;
            if (t == SEQT - 1) {
                out[OUT_HN + ((size_t)dir * BATCH + bh * 16 + pb) * HID + j0 + pu] = hnew;
                out[OUT_CN + ((size_t)dir * BATCH + bh * 16 + pb) * HID + j0 + pu] = creg;
            }
        }
        barh(barid);   // HO visible within the half

        // h write (32 threads x float4), then signal, then out (off crit path)
        if (tid7 < 32) {
            const int bl = tid7 >> 1;
            const int qq = (tid7 & 1) * 4;
            float4 v = *(const float4*)&HO[bl * 8 + qq];
            float* hdst = &g_hB[(t & 1) ^ 1][dir][bh][bl][0];
            *(float4*)&hdst[j0 + qq] = v;
        }
        barh(barid);   // h stores issued half-wide before release

        if (tid7 == 0) {
            asm volatile("red.release.gpu.add.s32 [%0], %1;"
                         :: "l"(mycnt), "r"(1));
        }

        if (tid7 < 32) {
            const int bl = tid7 >> 1;
            const int qq = (tid7 & 1) * 4;
            float4 v = *(const float4*)&HO[bl * 8 + qq];
            const int tout = dir ? (SEQT - 1 - t) : t;
            *(float4*)&out[((size_t)(bh * 16 + bl) * SEQT + tout) * (2 * HID)
                           + dir * HID + j0 + qq] = v;
        }
    }
}

// ---------------------------------------------------------------------------
// Launch
// ---------------------------------------------------------------------------
extern "C" void kernel_launch(void* const* d_in, const int* in_sizes, int n_in,
                              void* d_out, int out_size) {
    const float* x      = (const float*)d_in[0];
    const float* h0     = (const float*)d_in[1];
    const float* c0     = (const float*)d_in[2];
    const float* w_ih_f = (const float*)d_in[3];
    const float* w_hh_f = (const float*)d_in[4];
    const float* b_ih_f = (const float*)d_in[5];
    const float* b_hh_f = (const float*)d_in[6];
    const float* w_ih_r = (const float*)d_in[7];
    const float* w_hh_r = (const float*)d_in[8];
    const float* b_ih_r = (const float*)d_in[9];
    const float* b_hh_r = (const float*)d_in[10];
    float* out = (float*)d_out;

    cudaFuncSetAttribute(lstm_persistent_kernel,
                         cudaFuncAttributeMaxDynamicSharedMemorySize, SMEM_TOTAL);

    dim3 ggrid(G4 / BN, (SEQT * BATCH) / BM, 2);   // (32, 256, 2)
    gemm_ih_kernel<<<ggrid, 256>>>(x, h0, w_ih_f, w_ih_r,
                                   b_ih_f, b_hh_f, b_ih_r, b_hh_r);

    lstm_persistent_kernel<<<NBLK, 256, SMEM_TOTAL>>>(
        w_hh_f, w_hh_r, c0, out);
}